// round 5
// baseline (speedup 1.0000x reference)
#include <cuda_runtime.h>

// Scalar damped-Newton minimization of a degree-6 polynomial (serial, 1 thread).
// Exact reference semantics:
//   g2 = inf; while (g2 > 1e-12 && it < 100):
//     g=d1(x); h=d2(x); step = h>0 ? g/h : 0.1*g; x -= step; g2 = d1(x)^2
// (body always executes at least once; g at the top of body k equals g_new
//  from body k-1, so we carry it instead of recomputing).
//
// R4 findings: loop cost is NOT the bottleneck (iteration count is small);
// runtime is dominated by fixed launch/load/tail overhead. R5 = leanest exact
// loop + vectorized input loads:
//  - poly loaded as float4 + float2 + scalar (3 LDGs instead of 7)
//  - per-iter exit check overlaps the x-update chain (FSETP/BRA on g^2
//    resolves ~same cycle the rcp->FSEL->FMA chain produces x_new)
//  - rcp.approx.f32 for the Newton divide (fixed point & exit test exact)

#define MAX_ITER 100
#define GRAD_SQ_TOL 1e-12f

__device__ __forceinline__ float fast_rcp(float v) {
    float r;
    asm("rcp.approx.f32 %0, %1;" : "=f"(r) : "f"(v));
    return r;
}

__global__ void polymin_kernel(const float4* __restrict__ poly4,
                               const float*  __restrict__ x_init,
                               float* __restrict__ out) {
    // poly: 7 fp32 lowest-degree-first. Load as 4+2+1.
    const float4 p0 = poly4[0];                                     // c0..c3
    const float2 p1 = ((const float2*)poly4)[2];                    // c4,c5
    const float  c6 = ((const float*)poly4)[6];
    const float  x0 = x_init[0];

    // d1 = p' (a0..a5), d2 = p'' (b0..b4)
    const float a0 = p0.y,        a1 = p0.z * 2.0f, a2 = p0.w * 3.0f,
                a3 = p1.x * 4.0f, a4 = p1.y * 5.0f, a5 = c6  * 6.0f;
    const float b0 = a1,          b1 = a2 * 2.0f,   b2 = a3 * 3.0f,
                b3 = a4 * 4.0f,   b4 = a5 * 5.0f;

    float x  = x0;
    float x2 = x * x;
    // g = d1(x) for the first body execution (reference always enters: g2=inf)
    float g  = fmaf(fmaf(fmaf(a5, x, a4), x2, fmaf(a3, x, a2)), x2,
                    fmaf(a1, x, a0));

    #pragma unroll 1
    for (int it = 0; it < MAX_ITER; ++it) {
        // h = d2(x), Estrin off (x, x2)
        const float h = fmaf(fmaf(b4, x2, fmaf(b3, x, b2)), x2,
                             fmaf(b1, x, b0));
        const float r   = fast_rcp(h);
        const float mul = (h > 0.0f) ? r : 0.1f;   // pred-as-data FSEL
        x  = fmaf(-g, mul, x);
        x2 = x * x;
        // g_new = d1(x_new); exit check overlaps next chain
        g  = fmaf(fmaf(fmaf(a5, x, a4), x2, fmaf(a3, x, a2)), x2,
                  fmaf(a1, x, a0));
        if (!(g * g > GRAD_SQ_TOL)) break;
    }

    out[0] = x;
}

extern "C" void kernel_launch(void* const* d_in, const int* in_sizes, int n_in,
                              void* d_out, int out_size) {
    const float4* poly   = (const float4*)d_in[0];  // 7 fp32
    const float*  x_init = (const float*)d_in[1];   // 1 fp32
    polymin_kernel<<<1, 1>>>(poly, x_init, (float*)d_out);
}

// round 6
// speedup vs baseline: 1.0539x; 1.0539x over previous
#include <cuda_runtime.h>

// Scalar damped-Newton minimization of a degree-6 polynomial (serial, 1 thread).
// Exact reference semantics:
//   g2 = inf; while (g2 > 1e-12 && it < 100):
//     g=d1(x); h=d2(x); step = h>0 ? g/h : 0.1*g; x -= step; g2 = d1(x)^2
// g is carried across iterations (top-of-body g == previous g_new).
//
// R1-R4 established: runtime is ~90% fixed overhead (launch + L2-latency load
// chain + tail at idle DVFS clocks, plus ~2.6us graph-replay visible only in
// bench dur_us). Loop runs few iterations. This round: division-free select
// form so the g-path work and the x_fallback path run fully inside the 16-cyc
// MUFU.RCP shadow:
//   n  = x*h - g            (Newton numerator; x_new = n/h when h>0)
//   xA = n * rcp(h)         (@~32)
//   xB = x - 0.1*g          (@~12, off-path)
//   x  = h>0 ? xA : xB      (FSEL, pred-as-data)

#define MAX_ITER 100
#define GRAD_SQ_TOL 1e-12f

__device__ __forceinline__ float fast_rcp(float v) {
    float r;
    asm("rcp.approx.f32 %0, %1;" : "=f"(r) : "f"(v));
    return r;
}

__global__ void polymin_kernel(const float4* __restrict__ poly4,
                               const float*  __restrict__ x_init,
                               float* __restrict__ out) {
    // poly: 7 fp32 lowest-degree-first, loaded as 4+2+1 (one cache line)
    const float4 p0 = poly4[0];                   // c0..c3
    const float2 p1 = ((const float2*)poly4)[2];  // c4,c5
    const float  c6 = ((const float*)poly4)[6];
    const float  x0 = x_init[0];

    // d1 = p' (a0..a5), d2 = p'' (b0..b4)
    const float a0 = p0.y,        a1 = p0.z * 2.0f, a2 = p0.w * 3.0f,
                a3 = p1.x * 4.0f, a4 = p1.y * 5.0f, a5 = c6  * 6.0f;
    const float b0 = a1,          b1 = a2 * 2.0f,   b2 = a3 * 3.0f,
                b3 = a4 * 4.0f,   b4 = a5 * 5.0f;

    float x  = x0;
    float x2 = x * x;
    // g = d1(x) for the first body execution (reference always enters: g2=inf)
    float g  = fmaf(fmaf(fmaf(a5, x, a4), x2, fmaf(a3, x, a2)), x2,
                    fmaf(a1, x, a0));

    #pragma unroll 1
    for (int it = 0; it < MAX_ITER; ++it) {
        // h = d2(x): ((b4*x2 + (b3*x+b2))*x2 + (b1*x+b0)), h @~12
        const float h = fmaf(fmaf(b4, x2, fmaf(b3, x, b2)), x2,
                             fmaf(b1, x, b0));
        const float r  = fast_rcp(h);          // MUFU, in flight 16 cyc
        const float n  = fmaf(x, h, -g);       // overlaps MUFU shadow
        const float xB = fmaf(-0.1f, g, x);    // GD fallback, off-path
        const float xA = n * r;                // Newton result
        x  = (h > 0.0f) ? xA : xB;             // FSEL, pred-as-data
        x2 = x * x;
        // g_new = d1(x_new); exit compare overlaps next iteration's h-chain
        g  = fmaf(fmaf(fmaf(a5, x, a4), x2, fmaf(a3, x, a2)), x2,
                  fmaf(a1, x, a0));
        if (!(g * g > GRAD_SQ_TOL)) break;
    }

    out[0] = x;
}

extern "C" void kernel_launch(void* const* d_in, const int* in_sizes, int n_in,
                              void* d_out, int out_size) {
    const float4* poly   = (const float4*)d_in[0];  // 7 fp32
    const float*  x_init = (const float*)d_in[1];   // 1 fp32
    polymin_kernel<<<1, 1>>>(poly, x_init, (float*)d_out);
}